// round 14
// baseline (speedup 1.0000x reference)
#include <cuda_runtime.h>
#include <cuda_bf16.h>
#include <math.h>
#include <stdint.h>

// Problem constants
#define NV 50000
#define NE 640000
#define NHALF 320000
#define TILE_E 64
#define HALF_TILES (NHALF/TILE_E)   // 5000
#define GRID_HALF 148
#define R2 474
#define FIN 128
#define FOUT 128
#define CSTR 132                    // node-kernel padded fp32 stride

// edge-kernel smem layout (bytes); bf16 row stride 272B (17x16B -> LDSM conflict-free)
#define QSTRB 272
#define SM_QHI   0
#define SM_QLO   34816              // 128*272
#define SM_AHI   69632
#define SM_ALO   87040              // + 64*272
#define SM_SCALE 104448             // 256 floats
#define SM_DST   105472             // 64 ints
#define EDGE_SMEM 105728

// ---------------- scratch ----------------------------------------------------
__device__ float g_hacc[(size_t)NV * FOUT];
__device__ float g_h2[(size_t)NV * FOUT];
__device__ __align__(16) float g_Qin[FIN * FOUT];
__device__ __align__(16) float g_Qout[FIN * FOUT];
__device__ __align__(16) float g_w1a[FIN * 4];
__device__ __align__(16) float g_w2a[FIN * 4];
__device__ __align__(16) float g_ndot[(size_t)NV * 4];   // x_v . w2a[:,k]
__device__ float g_sum[FOUT];
__device__ float g_sumsq[FOUT];

// ---------------- helpers -----------------------------------------------------
__device__ __forceinline__ uint32_t smem_u32(const void* p) {
    uint32_t a;
    asm("{ .reg .u64 t; cvta.to.shared.u64 t, %1; cvt.u32.u64 %0, t; }" : "=r"(a) : "l"(p));
    return a;
}
__device__ __forceinline__ void ldsm_x4(uint32_t& r0, uint32_t& r1, uint32_t& r2,
                                        uint32_t& r3, uint32_t addr) {
    asm volatile("ldmatrix.sync.aligned.m8n8.x4.shared.b16 {%0,%1,%2,%3}, [%4];"
                 : "=r"(r0), "=r"(r1), "=r"(r2), "=r"(r3) : "r"(addr));
}
__device__ __forceinline__ void mma_bf16(float* c, const uint32_t* a,
                                         uint32_t b0, uint32_t b1) {
    asm volatile(
        "mma.sync.aligned.m16n8k16.row.col.f32.bf16.bf16.f32 "
        "{%0,%1,%2,%3}, {%4,%5,%6,%7}, {%8,%9}, {%0,%1,%2,%3};"
        : "+f"(c[0]), "+f"(c[1]), "+f"(c[2]), "+f"(c[3])
        : "r"(a[0]), "r"(a[1]), "r"(a[2]), "r"(a[3]), "r"(b0), "r"(b1));
}

// ---------------- kernel 0: zero scratch -------------------------------------
__global__ void zero_kernel() {
    int idx = blockIdx.x * blockDim.x + threadIdx.x;
    const int n4 = NV * FOUT / 4;
    float4 z = make_float4(0.f, 0.f, 0.f, 0.f);
    for (int i = idx; i < n4; i += gridDim.x * blockDim.x)
        ((float4*)g_hacc)[i] = z;
    if (idx < FOUT) { g_sum[idx] = 0.f; g_sumsq[idx] = 0.f; }
}

// ---------------- kernel 1a: fold attention weights --------------------------
__global__ void wfold_kernel(const float* __restrict__ node_w,
                             const float* __restrict__ node_rel_w,
                             const float* __restrict__ att_w) {
    int i = threadIdx.x;
    if (i >= 128) return;
#pragma unroll
    for (int k = 0; k < 4; k++) {
        float s1 = 0.f, s2 = 0.f;
#pragma unroll
        for (int d = 0; d < 32; d++) {
            s1 = fmaf(node_rel_w[k * 4096 + i * 32 + d], att_w[d], s1);
            s2 = fmaf(node_w[k * 4096 + i * 32 + d], att_w[32 + d], s2);
        }
        g_w1a[i * 4 + k] = s1;
        g_w2a[i * 4 + k] = s2;
    }
}

// ---------------- kernel 1b: fold projection weights -------------------------
__global__ void qfold_kernel(const float* __restrict__ node_rel_w,
                             const float* __restrict__ in_w,
                             const float* __restrict__ out_w) {
    __shared__ float nrw_s[128];
    int i = blockIdx.x;
    int tid = threadIdx.x;
    {
        int k = tid >> 5, d = tid & 31;
        nrw_s[tid] = node_rel_w[k * 4096 + i * 32 + d];
    }
    __syncthreads();
    int k = tid >> 5, o = tid & 31;
    float qi = 0.f, qo = 0.f;
#pragma unroll
    for (int d = 0; d < 32; d++) {
        float w = nrw_s[k * 32 + d];
        qi = fmaf(w, in_w[k * 1024 + d * 32 + o], qi);
        qo = fmaf(w, out_w[k * 1024 + d * 32 + o], qo);
    }
    g_Qin[i * 128 + tid] = qi;
    g_Qout[i * 128 + tid] = qo;
}

// ---------------- kernel 1c: per-node dst attention term (4 nodes/warp) ------
// ndot[v][k] = sum_i node_repr[v][i] * w2a[i][k]; 8 lanes per node, 12 shfl/4 nodes
__global__ void ndot_kernel(const float* __restrict__ node_repr) {
    int gwarp = (blockIdx.x * blockDim.x + threadIdx.x) >> 5;
    int lane = threadIdx.x & 31;
    int sub = lane >> 3;       // node within warp group (0..3)
    int l8 = lane & 7;
    int node = gwarp * 4 + sub;
    if (node >= NV) return;
    const float4* xr = (const float4*)(node_repr + (size_t)node * 128);
    const float4* w2 = (const float4*)g_w2a;
    float s0 = 0.f, s1 = 0.f, s2 = 0.f, s3 = 0.f;
#pragma unroll
    for (int j = 0; j < 4; j++) {
        float4 x = xr[l8 + 8 * j];
        const float4* wrow = w2 + (l8 + 8 * j) * 4;
        float4 wv;
        wv = wrow[0]; s0 = fmaf(x.x, wv.x, s0); s1 = fmaf(x.x, wv.y, s1); s2 = fmaf(x.x, wv.z, s2); s3 = fmaf(x.x, wv.w, s3);
        wv = wrow[1]; s0 = fmaf(x.y, wv.x, s0); s1 = fmaf(x.y, wv.y, s1); s2 = fmaf(x.y, wv.z, s2); s3 = fmaf(x.y, wv.w, s3);
        wv = wrow[2]; s0 = fmaf(x.z, wv.x, s0); s1 = fmaf(x.z, wv.y, s1); s2 = fmaf(x.z, wv.z, s2); s3 = fmaf(x.z, wv.w, s3);
        wv = wrow[3]; s0 = fmaf(x.w, wv.x, s0); s1 = fmaf(x.w, wv.y, s1); s2 = fmaf(x.w, wv.z, s2); s3 = fmaf(x.w, wv.w, s3);
    }
#pragma unroll
    for (int off = 1; off < 8; off <<= 1) {
        s0 += __shfl_xor_sync(0xFFFFFFFFu, s0, off);
        s1 += __shfl_xor_sync(0xFFFFFFFFu, s1, off);
        s2 += __shfl_xor_sync(0xFFFFFFFFu, s2, off);
        s3 += __shfl_xor_sync(0xFFFFFFFFu, s3, off);
    }
    if (l8 == 0)
        ((float4*)g_ndot)[node] = make_float4(s0, s1, s2, s3);
}

// ---------------- kernel 2: edge kernel (round-13 + MMA chain interleave) ----
__global__ void __launch_bounds__(256, 2) edge_kernel(
    const float* __restrict__ node_repr, const float* __restrict__ rel_repr,
    const int* __restrict__ src, const int* __restrict__ dst,
    const int* __restrict__ etype, const float* __restrict__ nrm) {
    extern __shared__ __align__(16) char smem[];
    uint32_t sb = smem_u32(smem);
    float* s_scale = (float*)(smem + SM_SCALE);
    int*   s_dst   = (int*)(smem + SM_DST);

    int tid = threadIdx.x;
    int wid = tid >> 5;
    int lane = tid & 31;
    int cta = blockIdx.x;
    int halfsel = (cta >= GRID_HALF) ? 1 : 0;
    int tile0 = cta - halfsel * GRID_HALF;
    const float* Q = halfsel ? g_Qout : g_Qin;

    // ---- stage Q as bf16 hi/lo, [n_phys][k], with intra-16-block column perm ----
    for (int idx = tid; idx < 16384; idx += 256) {
        int n = idx >> 7, k = idx & 127;
        int o = n & 15;
        int real = (n & ~15) | (((o & 6) << 1) | ((o & 8) >> 2) | (o & 1));
        float v = Q[k * 128 + real];
        __nv_bfloat16 hi = __float2bfloat16(v);
        __nv_bfloat16 lo = __float2bfloat16(v - __bfloat162float(hi));
        *(__nv_bfloat16*)(smem + SM_QHI + n * QSTRB + k * 2) = hi;
        *(__nv_bfloat16*)(smem + SM_QLO + n * QSTRB + k * 2) = lo;
    }

    // gather mapping: 4 threads per edge, interleaved 4-float slices
    int e    = tid >> 2;
    int l4   = tid & 3;

    // warp tiling: 4 row-bands x 2 col-halves (16 edges x 64 cols per warp)
    int rb = wid & 3, ch = wid >> 2;
    int eb = rb * 16;

    // ldmatrix lane addressing
    int arin = lane & 7;
    uint32_t a_row  = (uint32_t)(eb + ((lane >> 3) & 1) * 8 + arin);
    uint32_t a_coff = (uint32_t)((lane >> 4) * 16);
    uint32_t ahi_base = sb + SM_AHI + a_row * QSTRB + a_coff;
    uint32_t alo_base = sb + SM_ALO + a_row * QSTRB + a_coff;
    uint32_t b_row  = (uint32_t)((lane >> 4) * 8 + arin);
    uint32_t b_coff = (uint32_t)(((lane >> 3) & 1) * 16);

    for (int t = tile0; t < HALF_TILES; t += GRID_HALF) {
        __syncthreads();   // prior tile fully consumed (GEMM + scatter done)
        int e0 = (t + halfsel * HALF_TILES) * TILE_E;

        // ---- gather + compose + logits; store comp bf16 hi/lo ----
        {
            int isrc = __ldg(src + e0 + e);
            int idst = __ldg(dst + e0 + e);
            int iet  = __ldg(etype + e0 + e);
            float nv = __ldg(nrm + e0 + e);
            if (l4 == 0) s_dst[e] = idst;

            const float4* xs = (const float4*)(node_repr + (size_t)isrc * 128) + l4;
            const float4* rr = (const float4*)(rel_repr  + (size_t)iet  * 128) + l4;
            const float4* w1 = ((const float4*)g_w1a) + l4 * 4;
            float lg0 = 0.f, lg1 = 0.f, lg2 = 0.f, lg3 = 0.f;
#pragma unroll 4
            for (int q = 0; q < 8; q++) {
                float4 a = xs[q * 4], r4 = rr[q * 4];
                float4 c;
                c.x = a.x * r4.x; c.y = a.y * r4.y; c.z = a.z * r4.z; c.w = a.w * r4.w;
                {
                    __nv_bfloat162 h01 = __floats2bfloat162_rn(c.x, c.y);
                    __nv_bfloat162 h23 = __floats2bfloat162_rn(c.z, c.w);
                    __nv_bfloat162 l01 = __floats2bfloat162_rn(
                        c.x - __bfloat162float(h01.x), c.y - __bfloat162float(h01.y));
                    __nv_bfloat162 l23 = __floats2bfloat162_rn(
                        c.z - __bfloat162float(h23.x), c.w - __bfloat162float(h23.y));
                    uint32_t coff = (uint32_t)(e * QSTRB + (l4 * 4 + q * 16) * 2);
                    uint2 hv, lv;
                    hv.x = *(uint32_t*)&h01; hv.y = *(uint32_t*)&h23;
                    lv.x = *(uint32_t*)&l01; lv.y = *(uint32_t*)&l23;
                    *(uint2*)(smem + SM_AHI + coff) = hv;
                    *(uint2*)(smem + SM_ALO + coff) = lv;
                }
                int ib = q * 16;
                float4 wv;
                wv = w1[ib + 0]; lg0 = fmaf(c.x, wv.x, lg0); lg1 = fmaf(c.x, wv.y, lg1); lg2 = fmaf(c.x, wv.z, lg2); lg3 = fmaf(c.x, wv.w, lg3);
                wv = w1[ib + 1]; lg0 = fmaf(c.y, wv.x, lg0); lg1 = fmaf(c.y, wv.y, lg1); lg2 = fmaf(c.y, wv.z, lg2); lg3 = fmaf(c.y, wv.w, lg3);
                wv = w1[ib + 2]; lg0 = fmaf(c.z, wv.x, lg0); lg1 = fmaf(c.z, wv.y, lg1); lg2 = fmaf(c.z, wv.z, lg2); lg3 = fmaf(c.z, wv.w, lg3);
                wv = w1[ib + 3]; lg0 = fmaf(c.w, wv.x, lg0); lg1 = fmaf(c.w, wv.y, lg1); lg2 = fmaf(c.w, wv.z, lg2); lg3 = fmaf(c.w, wv.w, lg3);
            }
            lg0 += __shfl_xor_sync(0xFFFFFFFFu, lg0, 1);
            lg1 += __shfl_xor_sync(0xFFFFFFFFu, lg1, 1);
            lg2 += __shfl_xor_sync(0xFFFFFFFFu, lg2, 1);
            lg3 += __shfl_xor_sync(0xFFFFFFFFu, lg3, 1);
            lg0 += __shfl_xor_sync(0xFFFFFFFFu, lg0, 2);
            lg1 += __shfl_xor_sync(0xFFFFFFFFu, lg1, 2);
            lg2 += __shfl_xor_sync(0xFFFFFFFFu, lg2, 2);
            lg3 += __shfl_xor_sync(0xFFFFFFFFu, lg3, 2);
            if (l4 == 0) {
                float4 nd = __ldg(((const float4*)g_ndot) + idst);
                float l0 = fmaxf(lg0 + nd.x, 0.f);
                float l1 = fmaxf(lg1 + nd.y, 0.f);
                float l2 = fmaxf(lg2 + nd.z, 0.f);
                float l3 = fmaxf(lg3 + nd.w, 0.f);
                float e0x = expf(l0), e1x = expf(l1), e2x = expf(l2), e3x = expf(l3);
                float inv = nv / (e0x + e1x + e2x + e3x);   // /3 applied in node kernel
                s_scale[e * 4 + 0] = e0x * inv;
                s_scale[e * 4 + 1] = e1x * inv;
                s_scale[e * 4 + 2] = e2x * inv;
                s_scale[e * 4 + 3] = e3x * inv;
            }
        }
        __syncthreads();

        // ---- GEMM: 16 edges x 64 cols per warp, K=128, 3 bf16-split passes ----
        float c[8][4];
#pragma unroll
        for (int nt = 0; nt < 8; nt++)
#pragma unroll
            for (int j = 0; j < 4; j++) c[nt][j] = 0.f;

#pragma unroll 1
        for (int k = 0; k < 8; k++) {
            uint32_t ahi[4], alo[4];
            ldsm_x4(ahi[0], ahi[1], ahi[2], ahi[3], ahi_base + k * 32);
            ldsm_x4(alo[0], alo[1], alo[2], alo[3], alo_base + k * 32);
#pragma unroll
            for (int np = 0; np < 4; np++) {
                int nb = ch * 64 + np * 16;
                uint32_t bh[4], bl[4];
                uint32_t boff = (uint32_t)(nb + b_row) * QSTRB + b_coff + k * 32;
                ldsm_x4(bh[0], bh[1], bh[2], bh[3], sb + SM_QHI + boff);
                ldsm_x4(bl[0], bl[1], bl[2], bl[3], sb + SM_QLO + boff);
                // interleaved accumulator chains (RAW spacing 2)
                mma_bf16(c[2 * np],     ahi, bh[0], bh[1]);
                mma_bf16(c[2 * np + 1], ahi, bh[2], bh[3]);
                mma_bf16(c[2 * np],     ahi, bl[0], bl[1]);
                mma_bf16(c[2 * np + 1], ahi, bl[2], bl[3]);
                mma_bf16(c[2 * np],     alo, bh[0], bh[1]);
                mma_bf16(c[2 * np + 1], alo, bh[2], bh[3]);
            }
        }

        // ---- scale + scatter: red.v4 on 4 consecutive real cols per quad ----
        {
            int er0 = eb + (lane >> 2);
            int er1 = er0 + 8;
            int q4 = (lane & 3) * 4;
            float* hp0 = g_hacc + (size_t)s_dst[er0] * 128;
            float* hp1 = g_hacc + (size_t)s_dst[er1] * 128;
            const float* sp0 = s_scale + er0 * 4;
            const float* sp1 = s_scale + er1 * 4;
#pragma unroll
            for (int np = 0; np < 4; np++) {
                int nbase = ch * 64 + np * 16 + q4;
                int kfac = nbase >> 5;
                float s0 = sp0[kfac], s1 = sp1[kfac];
                asm volatile("red.global.add.v4.f32 [%0], {%1, %2, %3, %4};"
                    :: "l"(hp0 + nbase),
                       "f"(c[2 * np][0] * s0), "f"(c[2 * np][1] * s0),
                       "f"(c[2 * np + 1][0] * s0), "f"(c[2 * np + 1][1] * s0)
                    : "memory");
                asm volatile("red.global.add.v4.f32 [%0], {%1, %2, %3, %4};"
                    :: "l"(hp1 + nbase),
                       "f"(c[2 * np][2] * s1), "f"(c[2 * np][3] * s1),
                       "f"(c[2 * np + 1][2] * s1), "f"(c[2 * np + 1][3] * s1)
                    : "memory");
            }
        }
    }
}

// ---------------- kernel 3: node kernel (self-loop GEMM + fused BN stats) ---
// Ws staging removed: loop_w read via __ldg (L1-resident, 64KB).
// smem = t + sh + colsum/colsq = ~68.6KB -> 3 CTAs/SM.
__global__ void __launch_bounds__(128) node_kernel(
    const float* __restrict__ loop_rel, const float* __restrict__ loop_w,
    const float* __restrict__ bias) {
    extern __shared__ float sm[];
    float* t      = sm;                 // 64*CSTR
    float* sh     = t + 64 * CSTR;      // 64*CSTR
    float* colsum = sh + 64 * CSTR;     // 128
    float* colsq  = colsum + 128;       // 128

    int tid = threadIdx.x;
    int row0 = blockIdx.x * 64;

    if (tid < 128) { colsum[tid] = 0.f; colsq[tid] = 0.f; }

    {
        int e = tid >> 1;
        int ioff = (tid & 1) * 64;
        int row = row0 + e;
        float* tp = t + e * CSTR + ioff;
        float* hp = sh + e * CSTR + ioff;
        if (row < NV) {
            const float4* hv4 = (const float4*)(g_hacc + (size_t)row * 128 + ioff);
            const float4* lr4 = (const float4*)(loop_rel + ioff);
#pragma unroll
            for (int q = 0; q < 16; q++) {
                float4 hh = hv4[q];
                hh.x *= (1.f / 3.f); hh.y *= (1.f / 3.f); hh.z *= (1.f / 3.f); hh.w *= (1.f / 3.f);
                *(float4*)(hp + q * 4) = hh;
                float4 lr = lr4[q];
                float4 tv;
                tv.x = hh.x * lr.x; tv.y = hh.y * lr.y; tv.z = hh.z * lr.z; tv.w = hh.w * lr.w;
                *(float4*)(tp + q * 4) = tv;
            }
        } else {
            float4 z = make_float4(0.f, 0.f, 0.f, 0.f);
#pragma unroll
            for (int q = 0; q < 16; q++) {
                *(float4*)(hp + q * 4) = z;
                *(float4*)(tp + q * 4) = z;
            }
        }
    }
    __syncthreads();

    int c4 = tid & 15, r = tid >> 4;
    float acc[8][8];
#pragma unroll
    for (int u = 0; u < 8; u++)
#pragma unroll
        for (int m = 0; m < 8; m++) acc[u][m] = 0.f;

    const float* ap = t + (r * 8) * CSTR;
    const float* bp = loop_w + c4 * 4;
#pragma unroll 1
    for (int k = 0; k < 128; k += 4) {
#pragma unroll
        for (int kk = 0; kk < 4; kk++) {
            const float* brow = bp + (k + kk) * 128;
            float4 b0 = __ldg((const float4*)brow);
            float4 b1 = __ldg((const float4*)(brow + 64));
            float bv[8];
            bv[0] = b0.x; bv[1] = b0.y; bv[2] = b0.z; bv[3] = b0.w;
            bv[4] = b1.x; bv[5] = b1.y; bv[6] = b1.z; bv[7] = b1.w;
#pragma unroll
            for (int u = 0; u < 8; u++) {
                float av = ap[u * CSTR + k + kk];
#pragma unroll
                for (int m = 0; m < 8; m++) acc[u][m] = fmaf(av, bv[m], acc[u][m]);
            }
        }
    }

    float psum[8], psq[8];
#pragma unroll
    for (int m = 0; m < 8; m++) { psum[m] = 0.f; psq[m] = 0.f; }
#pragma unroll
    for (int u = 0; u < 8; u++) {
        int e = r * 8 + u;
        int row = row0 + e;
        if (row < NV) {
#pragma unroll
            for (int m = 0; m < 8; m++) {
                int col = (m < 4) ? (c4 * 4 + m) : (64 + c4 * 4 + m - 4);
                float v = sh[e * CSTR + col] + acc[u][m] * (1.f / 3.f) + bias[col];
                g_h2[(size_t)row * 128 + col] = v;
                psum[m] += v;
                psq[m] = fmaf(v, v, psq[m]);
            }
        }
    }
#pragma unroll
    for (int m = 0; m < 8; m++) {
        int col = (m < 4) ? (c4 * 4 + m) : (64 + c4 * 4 + m - 4);
        atomicAdd(&colsum[col], psum[m]);
        atomicAdd(&colsq[col], psq[m]);
    }
    __syncthreads();
    if (tid < 128) {
        atomicAdd(&g_sum[tid], colsum[tid]);
        atomicAdd(&g_sumsq[tid], colsq[tid]);
    }
}

// ---------------- kernel 4: batchnorm + tanh ---------------------------------
__global__ void finalize_kernel(const float* __restrict__ gamma,
                                const float* __restrict__ beta,
                                float* __restrict__ out) {
    __shared__ float sa[128], sb_[128];
    int tid = threadIdx.x;
    if (tid < 128) {
        float mean = g_sum[tid] * (1.f / NV);
        float var = g_sumsq[tid] * (1.f / NV) - mean * mean;
        float a = gamma[tid] * rsqrtf(var + 1e-5f);
        sa[tid] = a;
        sb_[tid] = beta[tid] - mean * a;
    }
    __syncthreads();
    const int n4 = NV * FOUT / 4;
    for (int i = blockIdx.x * blockDim.x + tid; i < n4; i += gridDim.x * blockDim.x) {
        float4 v = ((const float4*)g_h2)[i];
        int c0 = (i * 4) & 127;
        float4 y;
        y.x = tanhf(fmaf(v.x, sa[c0 + 0], sb_[c0 + 0]));
        y.y = tanhf(fmaf(v.y, sa[c0 + 1], sb_[c0 + 1]));
        y.z = tanhf(fmaf(v.z, sa[c0 + 2], sb_[c0 + 2]));
        y.w = tanhf(fmaf(v.w, sa[c0 + 3], sb_[c0 + 3]));
        ((float4*)out)[i] = y;
    }
}

// ---------------- kernel 5: rel_out = rel_repr @ w_rel -----------------------
__global__ void relout_kernel(const float* __restrict__ rel_repr,
                              const float* __restrict__ w_rel,
                              float* __restrict__ out) {
    __shared__ float rrow[128];
    int b = blockIdx.x, tid = threadIdx.x;
    rrow[tid] = rel_repr[b * 128 + tid];
    __syncthreads();
    float s = 0.f;
#pragma unroll 4
    for (int i = 0; i < 128; i++) s = fmaf(rrow[i], w_rel[i * 128 + tid], s);
    out[(size_t)NV * FOUT + b * 128 + tid] = s;
}

// ---------------- host launcher ----------------------------------------------
extern "C" void kernel_launch(void* const* d_in, const int* in_sizes, int n_in,
                              void* d_out, int out_size) {
    const float* node_repr  = (const float*)d_in[0];
    const float* rel_repr   = (const float*)d_in[1];
    const int*   src        = (const int*)d_in[2];
    const int*   dst        = (const int*)d_in[3];
    const int*   etype      = (const int*)d_in[4];
    const float* nrm        = (const float*)d_in[5];
    const float* node_w     = (const float*)d_in[6];
    const float* node_rel_w = (const float*)d_in[7];
    const float* in_w       = (const float*)d_in[8];
    const float* out_w      = (const float*)d_in[9];
    const float* att_w      = (const float*)d_in[10];
    const float* loop_rel   = (const float*)d_in[11];
    const float* loop_w     = (const float*)d_in[12];
    const float* w_rel      = (const float*)d_in[13];
    const float* bias       = (const float*)d_in[14];
    const float* bn_gamma   = (const float*)d_in[15];
    const float* bn_beta    = (const float*)d_in[16];
    float* out = (float*)d_out;

    static const int NODE_SMEM = (2 * 64 * CSTR + 256) * 4;   // ~68.6 KB -> 3 CTAs/SM
    cudaFuncSetAttribute(edge_kernel, cudaFuncAttributeMaxDynamicSharedMemorySize, EDGE_SMEM);
    cudaFuncSetAttribute(node_kernel, cudaFuncAttributeMaxDynamicSharedMemorySize, NODE_SMEM);

    zero_kernel<<<512, 256>>>();
    wfold_kernel<<<1, 128>>>(node_w, node_rel_w, att_w);
    qfold_kernel<<<128, 128>>>(node_rel_w, in_w, out_w);
    ndot_kernel<<<(NV / 4 + 7) / 8 + 1, 256>>>(node_repr);
    edge_kernel<<<2 * GRID_HALF, 256, EDGE_SMEM>>>(node_repr, rel_repr, src, dst, etype, nrm);
    node_kernel<<<(NV + 63) / 64, 128, NODE_SMEM>>>(loop_rel, loop_w, bias);
    finalize_kernel<<<1024, 256>>>(bn_gamma, bn_beta, out);
    relout_kernel<<<R2, 128>>>(rel_repr, w_rel, out);
}

// round 15
// speedup vs baseline: 1.0083x; 1.0083x over previous
#include <cuda_runtime.h>
#include <cuda_bf16.h>
#include <math.h>
#include <stdint.h>

// Problem constants
#define NV 50000
#define NE 640000
#define NHALF 320000
#define TILE_E 64
#define HALF_TILES (NHALF/TILE_E)   // 5000
#define GRID_HALF 148
#define R2 474
#define FIN 128
#define FOUT 128
#define CSTR 132                    // node-kernel padded fp32 stride

// edge-kernel smem layout (bytes); bf16 row stride 272B (17x16B -> LDSM conflict-free)
#define QSTRB 272
#define SM_QHI   0
#define SM_QLO   34816              // 128*272
#define SM_AHI   69632
#define SM_ALO   87040              // + 64*272
#define SM_SCALE 104448             // 256 floats
#define SM_DST   105472             // 64 ints
#define EDGE_SMEM 105728

// ---------------- scratch ----------------------------------------------------
__device__ float g_hacc[(size_t)NV * FOUT];
__device__ float g_h2[(size_t)NV * FOUT];
__device__ __align__(16) float g_Qin[FIN * FOUT];
__device__ __align__(16) float g_Qout[FIN * FOUT];
__device__ __align__(16) float g_w1a[FIN * 4];
__device__ __align__(16) float g_w2a[FIN * 4];
__device__ __align__(16) float g_ndot[(size_t)NV * 4];   // x_v . w2a[:,k]
__device__ float g_sum[FOUT];
__device__ float g_sumsq[FOUT];

// ---------------- helpers -----------------------------------------------------
__device__ __forceinline__ uint32_t smem_u32(const void* p) {
    uint32_t a;
    asm("{ .reg .u64 t; cvta.to.shared.u64 t, %1; cvt.u32.u64 %0, t; }" : "=r"(a) : "l"(p));
    return a;
}
__device__ __forceinline__ void ldsm_x4(uint32_t& r0, uint32_t& r1, uint32_t& r2,
                                        uint32_t& r3, uint32_t addr) {
    asm volatile("ldmatrix.sync.aligned.m8n8.x4.shared.b16 {%0,%1,%2,%3}, [%4];"
                 : "=r"(r0), "=r"(r1), "=r"(r2), "=r"(r3) : "r"(addr));
}
__device__ __forceinline__ void mma_bf16(float* c, const uint32_t* a,
                                         uint32_t b0, uint32_t b1) {
    asm volatile(
        "mma.sync.aligned.m16n8k16.row.col.f32.bf16.bf16.f32 "
        "{%0,%1,%2,%3}, {%4,%5,%6,%7}, {%8,%9}, {%0,%1,%2,%3};"
        : "+f"(c[0]), "+f"(c[1]), "+f"(c[2]), "+f"(c[3])
        : "r"(a[0]), "r"(a[1]), "r"(a[2]), "r"(a[3]), "r"(b0), "r"(b1));
}

// ---------------- kernel 0: zero scratch -------------------------------------
__global__ void zero_kernel() {
    int idx = blockIdx.x * blockDim.x + threadIdx.x;
    const int n4 = NV * FOUT / 4;
    float4 z = make_float4(0.f, 0.f, 0.f, 0.f);
    for (int i = idx; i < n4; i += gridDim.x * blockDim.x)
        ((float4*)g_hacc)[i] = z;
    if (idx < FOUT) { g_sum[idx] = 0.f; g_sumsq[idx] = 0.f; }
}

// ---------------- kernel 1a: fold attention weights --------------------------
__global__ void wfold_kernel(const float* __restrict__ node_w,
                             const float* __restrict__ node_rel_w,
                             const float* __restrict__ att_w) {
    int i = threadIdx.x;
    if (i >= 128) return;
#pragma unroll
    for (int k = 0; k < 4; k++) {
        float s1 = 0.f, s2 = 0.f;
#pragma unroll
        for (int d = 0; d < 32; d++) {
            s1 = fmaf(node_rel_w[k * 4096 + i * 32 + d], att_w[d], s1);
            s2 = fmaf(node_w[k * 4096 + i * 32 + d], att_w[32 + d], s2);
        }
        g_w1a[i * 4 + k] = s1;
        g_w2a[i * 4 + k] = s2;
    }
}

// ---------------- kernel 1b: fold projection weights -------------------------
__global__ void qfold_kernel(const float* __restrict__ node_rel_w,
                             const float* __restrict__ in_w,
                             const float* __restrict__ out_w) {
    __shared__ float nrw_s[128];
    int i = blockIdx.x;
    int tid = threadIdx.x;
    {
        int k = tid >> 5, d = tid & 31;
        nrw_s[tid] = node_rel_w[k * 4096 + i * 32 + d];
    }
    __syncthreads();
    int k = tid >> 5, o = tid & 31;
    float qi = 0.f, qo = 0.f;
#pragma unroll
    for (int d = 0; d < 32; d++) {
        float w = nrw_s[k * 32 + d];
        qi = fmaf(w, in_w[k * 1024 + d * 32 + o], qi);
        qo = fmaf(w, out_w[k * 1024 + d * 32 + o], qo);
    }
    g_Qin[i * 128 + tid] = qi;
    g_Qout[i * 128 + tid] = qo;
}

// ---------------- kernel 1c: per-node dst attention term (4 nodes/warp) ------
__global__ void ndot_kernel(const float* __restrict__ node_repr) {
    int gwarp = (blockIdx.x * blockDim.x + threadIdx.x) >> 5;
    int lane = threadIdx.x & 31;
    int sub = lane >> 3;       // node within warp group (0..3)
    int l8 = lane & 7;
    int node = gwarp * 4 + sub;
    if (node >= NV) return;
    const float4* xr = (const float4*)(node_repr + (size_t)node * 128);
    const float4* w2 = (const float4*)g_w2a;
    float s0 = 0.f, s1 = 0.f, s2 = 0.f, s3 = 0.f;
#pragma unroll
    for (int j = 0; j < 4; j++) {
        float4 x = xr[l8 + 8 * j];
        const float4* wrow = w2 + (l8 + 8 * j) * 4;
        float4 wv;
        wv = wrow[0]; s0 = fmaf(x.x, wv.x, s0); s1 = fmaf(x.x, wv.y, s1); s2 = fmaf(x.x, wv.z, s2); s3 = fmaf(x.x, wv.w, s3);
        wv = wrow[1]; s0 = fmaf(x.y, wv.x, s0); s1 = fmaf(x.y, wv.y, s1); s2 = fmaf(x.y, wv.z, s2); s3 = fmaf(x.y, wv.w, s3);
        wv = wrow[2]; s0 = fmaf(x.z, wv.x, s0); s1 = fmaf(x.z, wv.y, s1); s2 = fmaf(x.z, wv.z, s2); s3 = fmaf(x.z, wv.w, s3);
        wv = wrow[3]; s0 = fmaf(x.w, wv.x, s0); s1 = fmaf(x.w, wv.y, s1); s2 = fmaf(x.w, wv.z, s2); s3 = fmaf(x.w, wv.w, s3);
    }
#pragma unroll
    for (int off = 1; off < 8; off <<= 1) {
        s0 += __shfl_xor_sync(0xFFFFFFFFu, s0, off);
        s1 += __shfl_xor_sync(0xFFFFFFFFu, s1, off);
        s2 += __shfl_xor_sync(0xFFFFFFFFu, s2, off);
        s3 += __shfl_xor_sync(0xFFFFFFFFu, s3, off);
    }
    if (l8 == 0)
        ((float4*)g_ndot)[node] = make_float4(s0, s1, s2, s3);
}

// ---------------- kernel 2: edge kernel (round-13 exact MMA order) -----------
__global__ void __launch_bounds__(256, 2) edge_kernel(
    const float* __restrict__ node_repr, const float* __restrict__ rel_repr,
    const int* __restrict__ src, const int* __restrict__ dst,
    const int* __restrict__ etype, const float* __restrict__ nrm) {
    extern __shared__ __align__(16) char smem[];
    uint32_t sb = smem_u32(smem);
    float* s_scale = (float*)(smem + SM_SCALE);
    int*   s_dst   = (int*)(smem + SM_DST);

    int tid = threadIdx.x;
    int wid = tid >> 5;
    int lane = tid & 31;
    int cta = blockIdx.x;
    int halfsel = (cta >= GRID_HALF) ? 1 : 0;
    int tile0 = cta - halfsel * GRID_HALF;
    const float* Q = halfsel ? g_Qout : g_Qin;

    // ---- stage Q as bf16 hi/lo, [n_phys][k], with intra-16-block column perm ----
    for (int idx = tid; idx < 16384; idx += 256) {
        int n = idx >> 7, k = idx & 127;
        int o = n & 15;
        int real = (n & ~15) | (((o & 6) << 1) | ((o & 8) >> 2) | (o & 1));
        float v = Q[k * 128 + real];
        __nv_bfloat16 hi = __float2bfloat16(v);
        __nv_bfloat16 lo = __float2bfloat16(v - __bfloat162float(hi));
        *(__nv_bfloat16*)(smem + SM_QHI + n * QSTRB + k * 2) = hi;
        *(__nv_bfloat16*)(smem + SM_QLO + n * QSTRB + k * 2) = lo;
    }

    // gather mapping: 4 threads per edge, interleaved 4-float slices
    int e    = tid >> 2;
    int l4   = tid & 3;

    // warp tiling: 4 row-bands x 2 col-halves (16 edges x 64 cols per warp)
    int rb = wid & 3, ch = wid >> 2;
    int eb = rb * 16;

    // ldmatrix lane addressing
    int arin = lane & 7;
    uint32_t a_row  = (uint32_t)(eb + ((lane >> 3) & 1) * 8 + arin);
    uint32_t a_coff = (uint32_t)((lane >> 4) * 16);
    uint32_t ahi_base = sb + SM_AHI + a_row * QSTRB + a_coff;
    uint32_t alo_base = sb + SM_ALO + a_row * QSTRB + a_coff;
    uint32_t b_row  = (uint32_t)((lane >> 4) * 8 + arin);
    uint32_t b_coff = (uint32_t)(((lane >> 3) & 1) * 16);

    for (int t = tile0; t < HALF_TILES; t += GRID_HALF) {
        __syncthreads();   // prior tile fully consumed (GEMM + scatter done)
        int e0 = (t + halfsel * HALF_TILES) * TILE_E;

        // ---- gather + compose + logits; store comp bf16 hi/lo ----
        {
            int isrc = __ldg(src + e0 + e);
            int idst = __ldg(dst + e0 + e);
            int iet  = __ldg(etype + e0 + e);
            float nv = __ldg(nrm + e0 + e);
            if (l4 == 0) s_dst[e] = idst;

            const float4* xs = (const float4*)(node_repr + (size_t)isrc * 128) + l4;
            const float4* rr = (const float4*)(rel_repr  + (size_t)iet  * 128) + l4;
            const float4* w1 = ((const float4*)g_w1a) + l4 * 4;
            float lg0 = 0.f, lg1 = 0.f, lg2 = 0.f, lg3 = 0.f;
#pragma unroll 4
            for (int q = 0; q < 8; q++) {
                float4 a = xs[q * 4], r4 = rr[q * 4];
                float4 c;
                c.x = a.x * r4.x; c.y = a.y * r4.y; c.z = a.z * r4.z; c.w = a.w * r4.w;
                {
                    __nv_bfloat162 h01 = __floats2bfloat162_rn(c.x, c.y);
                    __nv_bfloat162 h23 = __floats2bfloat162_rn(c.z, c.w);
                    __nv_bfloat162 l01 = __floats2bfloat162_rn(
                        c.x - __bfloat162float(h01.x), c.y - __bfloat162float(h01.y));
                    __nv_bfloat162 l23 = __floats2bfloat162_rn(
                        c.z - __bfloat162float(h23.x), c.w - __bfloat162float(h23.y));
                    uint32_t coff = (uint32_t)(e * QSTRB + (l4 * 4 + q * 16) * 2);
                    uint2 hv, lv;
                    hv.x = *(uint32_t*)&h01; hv.y = *(uint32_t*)&h23;
                    lv.x = *(uint32_t*)&l01; lv.y = *(uint32_t*)&l23;
                    *(uint2*)(smem + SM_AHI + coff) = hv;
                    *(uint2*)(smem + SM_ALO + coff) = lv;
                }
                int ib = q * 16;
                float4 wv;
                wv = w1[ib + 0]; lg0 = fmaf(c.x, wv.x, lg0); lg1 = fmaf(c.x, wv.y, lg1); lg2 = fmaf(c.x, wv.z, lg2); lg3 = fmaf(c.x, wv.w, lg3);
                wv = w1[ib + 1]; lg0 = fmaf(c.y, wv.x, lg0); lg1 = fmaf(c.y, wv.y, lg1); lg2 = fmaf(c.y, wv.z, lg2); lg3 = fmaf(c.y, wv.w, lg3);
                wv = w1[ib + 2]; lg0 = fmaf(c.z, wv.x, lg0); lg1 = fmaf(c.z, wv.y, lg1); lg2 = fmaf(c.z, wv.z, lg2); lg3 = fmaf(c.z, wv.w, lg3);
                wv = w1[ib + 3]; lg0 = fmaf(c.w, wv.x, lg0); lg1 = fmaf(c.w, wv.y, lg1); lg2 = fmaf(c.w, wv.z, lg2); lg3 = fmaf(c.w, wv.w, lg3);
            }
            lg0 += __shfl_xor_sync(0xFFFFFFFFu, lg0, 1);
            lg1 += __shfl_xor_sync(0xFFFFFFFFu, lg1, 1);
            lg2 += __shfl_xor_sync(0xFFFFFFFFu, lg2, 1);
            lg3 += __shfl_xor_sync(0xFFFFFFFFu, lg3, 1);
            lg0 += __shfl_xor_sync(0xFFFFFFFFu, lg0, 2);
            lg1 += __shfl_xor_sync(0xFFFFFFFFu, lg1, 2);
            lg2 += __shfl_xor_sync(0xFFFFFFFFu, lg2, 2);
            lg3 += __shfl_xor_sync(0xFFFFFFFFu, lg3, 2);
            if (l4 == 0) {
                float4 nd = __ldg(((const float4*)g_ndot) + idst);
                float l0 = fmaxf(lg0 + nd.x, 0.f);
                float l1 = fmaxf(lg1 + nd.y, 0.f);
                float l2 = fmaxf(lg2 + nd.z, 0.f);
                float l3 = fmaxf(lg3 + nd.w, 0.f);
                float e0x = expf(l0), e1x = expf(l1), e2x = expf(l2), e3x = expf(l3);
                float inv = nv / (e0x + e1x + e2x + e3x);   // /3 applied in node kernel
                s_scale[e * 4 + 0] = e0x * inv;
                s_scale[e * 4 + 1] = e1x * inv;
                s_scale[e * 4 + 2] = e2x * inv;
                s_scale[e * 4 + 3] = e3x * inv;
            }
        }
        __syncthreads();

        // ---- GEMM: 16 edges x 64 cols per warp, K=128, 3 bf16-split passes ----
        float c[8][4];
#pragma unroll
        for (int nt = 0; nt < 8; nt++)
#pragma unroll
            for (int j = 0; j < 4; j++) c[nt][j] = 0.f;

#pragma unroll 1
        for (int k = 0; k < 8; k++) {
            uint32_t ahi[4], alo[4];
            ldsm_x4(ahi[0], ahi[1], ahi[2], ahi[3], ahi_base + k * 32);
            ldsm_x4(alo[0], alo[1], alo[2], alo[3], alo_base + k * 32);
#pragma unroll
            for (int np = 0; np < 4; np++) {
                int nb = ch * 64 + np * 16;
                uint32_t bh[4], bl[4];
                uint32_t boff = (uint32_t)(nb + b_row) * QSTRB + b_coff + k * 32;
                ldsm_x4(bh[0], bh[1], bh[2], bh[3], sb + SM_QHI + boff);
                ldsm_x4(bl[0], bl[1], bl[2], bl[3], sb + SM_QLO + boff);
                mma_bf16(c[2 * np],     ahi, bh[0], bh[1]);
                mma_bf16(c[2 * np],     ahi, bl[0], bl[1]);
                mma_bf16(c[2 * np],     alo, bh[0], bh[1]);
                mma_bf16(c[2 * np + 1], ahi, bh[2], bh[3]);
                mma_bf16(c[2 * np + 1], ahi, bl[2], bl[3]);
                mma_bf16(c[2 * np + 1], alo, bh[2], bh[3]);
            }
        }

        // ---- scale + scatter: red.v4 on 4 consecutive real cols per quad ----
        {
            int er0 = eb + (lane >> 2);
            int er1 = er0 + 8;
            int q4 = (lane & 3) * 4;
            float* hp0 = g_hacc + (size_t)s_dst[er0] * 128;
            float* hp1 = g_hacc + (size_t)s_dst[er1] * 128;
            const float* sp0 = s_scale + er0 * 4;
            const float* sp1 = s_scale + er1 * 4;
#pragma unroll
            for (int np = 0; np < 4; np++) {
                int nbase = ch * 64 + np * 16 + q4;
                int kfac = nbase >> 5;
                float s0 = sp0[kfac], s1 = sp1[kfac];
                asm volatile("red.global.add.v4.f32 [%0], {%1, %2, %3, %4};"
                    :: "l"(hp0 + nbase),
                       "f"(c[2 * np][0] * s0), "f"(c[2 * np][1] * s0),
                       "f"(c[2 * np + 1][0] * s0), "f"(c[2 * np + 1][1] * s0)
                    : "memory");
                asm volatile("red.global.add.v4.f32 [%0], {%1, %2, %3, %4};"
                    :: "l"(hp1 + nbase),
                       "f"(c[2 * np][2] * s1), "f"(c[2 * np][3] * s1),
                       "f"(c[2 * np + 1][2] * s1), "f"(c[2 * np + 1][3] * s1)
                    : "memory");
            }
        }
    }
}

// ---------------- kernel 3: node kernel (self-loop GEMM + fused BN stats) ---
// loop_w read via __ldg (L1-resident, 64KB). smem ~68.6KB -> 3 CTAs/SM.
__global__ void __launch_bounds__(128) node_kernel(
    const float* __restrict__ loop_rel, const float* __restrict__ loop_w,
    const float* __restrict__ bias) {
    extern __shared__ float sm[];
    float* t      = sm;                 // 64*CSTR
    float* sh     = t + 64 * CSTR;      // 64*CSTR
    float* colsum = sh + 64 * CSTR;     // 128
    float* colsq  = colsum + 128;       // 128

    int tid = threadIdx.x;
    int row0 = blockIdx.x * 64;

    if (tid < 128) { colsum[tid] = 0.f; colsq[tid] = 0.f; }

    {
        int e = tid >> 1;
        int ioff = (tid & 1) * 64;
        int row = row0 + e;
        float* tp = t + e * CSTR + ioff;
        float* hp = sh + e * CSTR + ioff;
        if (row < NV) {
            const float4* hv4 = (const float4*)(g_hacc + (size_t)row * 128 + ioff);
            const float4* lr4 = (const float4*)(loop_rel + ioff);
#pragma unroll
            for (int q = 0; q < 16; q++) {
                float4 hh = hv4[q];
                hh.x *= (1.f / 3.f); hh.y *= (1.f / 3.f); hh.z *= (1.f / 3.f); hh.w *= (1.f / 3.f);
                *(float4*)(hp + q * 4) = hh;
                float4 lr = lr4[q];
                float4 tv;
                tv.x = hh.x * lr.x; tv.y = hh.y * lr.y; tv.z = hh.z * lr.z; tv.w = hh.w * lr.w;
                *(float4*)(tp + q * 4) = tv;
            }
        } else {
            float4 z = make_float4(0.f, 0.f, 0.f, 0.f);
#pragma unroll
            for (int q = 0; q < 16; q++) {
                *(float4*)(hp + q * 4) = z;
                *(float4*)(tp + q * 4) = z;
            }
        }
    }
    __syncthreads();

    int c4 = tid & 15, r = tid >> 4;
    float acc[8][8];
#pragma unroll
    for (int u = 0; u < 8; u++)
#pragma unroll
        for (int m = 0; m < 8; m++) acc[u][m] = 0.f;

    const float* ap = t + (r * 8) * CSTR;
    const float* bp = loop_w + c4 * 4;
#pragma unroll 1
    for (int k = 0; k < 128; k += 4) {
#pragma unroll
        for (int kk = 0; kk < 4; kk++) {
            const float* brow = bp + (k + kk) * 128;
            float4 b0 = __ldg((const float4*)brow);
            float4 b1 = __ldg((const float4*)(brow + 64));
            float bv[8];
            bv[0] = b0.x; bv[1] = b0.y; bv[2] = b0.z; bv[3] = b0.w;
            bv[4] = b1.x; bv[5] = b1.y; bv[6] = b1.z; bv[7] = b1.w;
#pragma unroll
            for (int u = 0; u < 8; u++) {
                float av = ap[u * CSTR + k + kk];
#pragma unroll
                for (int m = 0; m < 8; m++) acc[u][m] = fmaf(av, bv[m], acc[u][m]);
            }
        }
    }

    float psum[8], psq[8];
#pragma unroll
    for (int m = 0; m < 8; m++) { psum[m] = 0.f; psq[m] = 0.f; }
#pragma unroll
    for (int u = 0; u < 8; u++) {
        int e = r * 8 + u;
        int row = row0 + e;
        if (row < NV) {
#pragma unroll
            for (int m = 0; m < 8; m++) {
                int col = (m < 4) ? (c4 * 4 + m) : (64 + c4 * 4 + m - 4);
                float v = sh[e * CSTR + col] + acc[u][m] * (1.f / 3.f) + bias[col];
                g_h2[(size_t)row * 128 + col] = v;
                psum[m] += v;
                psq[m] = fmaf(v, v, psq[m]);
            }
        }
    }
#pragma unroll
    for (int m = 0; m < 8; m++) {
        int col = (m < 4) ? (c4 * 4 + m) : (64 + c4 * 4 + m - 4);
        atomicAdd(&colsum[col], psum[m]);
        atomicAdd(&colsq[col], psq[m]);
    }
    __syncthreads();
    if (tid < 128) {
        atomicAdd(&g_sum[tid], colsum[tid]);
        atomicAdd(&g_sumsq[tid], colsq[tid]);
    }
}

// ---------------- kernel 4: batchnorm + tanh ---------------------------------
__global__ void finalize_kernel(const float* __restrict__ gamma,
                                const float* __restrict__ beta,
                                float* __restrict__ out) {
    __shared__ float sa[128], sb_[128];
    int tid = threadIdx.x;
    if (tid < 128) {
        float mean = g_sum[tid] * (1.f / NV);
        float var = g_sumsq[tid] * (1.f / NV) - mean * mean;
        float a = gamma[tid] * rsqrtf(var + 1e-5f);
        sa[tid] = a;
        sb_[tid] = beta[tid] - mean * a;
    }
    __syncthreads();
    const int n4 = NV * FOUT / 4;
    for (int i = blockIdx.x * blockDim.x + tid; i < n4; i += gridDim.x * blockDim.x) {
        float4 v = ((const float4*)g_h2)[i];
        int c0 = (i * 4) & 127;
        float4 y;
        y.x = tanhf(fmaf(v.x, sa[c0 + 0], sb_[c0 + 0]));
        y.y = tanhf(fmaf(v.y, sa[c0 + 1], sb_[c0 + 1]));
        y.z = tanhf(fmaf(v.z, sa[c0 + 2], sb_[c0 + 2]));
        y.w = tanhf(fmaf(v.w, sa[c0 + 3], sb_[c0 + 3]));
        ((float4*)out)[i] = y;
    }
}

// ---------------- kernel 5: rel_out = rel_repr @ w_rel -----------------------
__global__ void relout_kernel(const float* __restrict__ rel_repr,
                              const float* __restrict__ w_rel,
                              float* __restrict__ out) {
    __shared__ float rrow[128];
    int b = blockIdx.x, tid = threadIdx.x;
    rrow[tid] = rel_repr[b * 128 + tid];
    __syncthreads();
    float s = 0.f;
#pragma unroll 4
    for (int i = 0; i < 128; i++) s = fmaf(rrow[i], w_rel[i * 128 + tid], s);
    out[(size_t)NV * FOUT + b * 128 + tid] = s;
}

// ---------------- host launcher ----------------------------------------------
extern "C" void kernel_launch(void* const* d_in, const int* in_sizes, int n_in,
                              void* d_out, int out_size) {
    const float* node_repr  = (const float*)d_in[0];
    const float* rel_repr   = (const float*)d_in[1];
    const int*   src        = (const int*)d_in[2];
    const int*   dst        = (const int*)d_in[3];
    const int*   etype      = (const int*)d_in[4];
    const float* nrm        = (const float*)d_in[5];
    const float* node_w     = (const float*)d_in[6];
    const float* node_rel_w = (const float*)d_in[7];
    const float* in_w       = (const float*)d_in[8];
    const float* out_w      = (const float*)d_in[9];
    const float* att_w      = (const float*)d_in[10];
    const float* loop_rel   = (const float*)d_in[11];
    const float* loop_w     = (const float*)d_in[12];
    const float* w_rel      = (const float*)d_in[13];
    const float* bias       = (const float*)d_in[14];
    const float* bn_gamma   = (const float*)d_in[15];
    const float* bn_beta    = (const float*)d_in[16];
    float* out = (float*)d_out;

    static const int NODE_SMEM = (2 * 64 * CSTR + 256) * 4;   // ~68.6 KB -> 3 CTAs/SM
    cudaFuncSetAttribute(edge_kernel, cudaFuncAttributeMaxDynamicSharedMemorySize, EDGE_SMEM);
    cudaFuncSetAttribute(node_kernel, cudaFuncAttributeMaxDynamicSharedMemorySize, NODE_SMEM);

    zero_kernel<<<512, 256>>>();
    wfold_kernel<<<1, 128>>>(node_w, node_rel_w, att_w);
    qfold_kernel<<<128, 128>>>(node_rel_w, in_w, out_w);
    ndot_kernel<<<(NV / 4 + 7) / 8 + 1, 256>>>(node_repr);
    edge_kernel<<<2 * GRID_HALF, 256, EDGE_SMEM>>>(node_repr, rel_repr, src, dst, etype, nrm);
    node_kernel<<<(NV + 63) / 64, 128, NODE_SMEM>>>(loop_rel, loop_w, bias);
    finalize_kernel<<<1024, 256>>>(bn_gamma, bn_beta, out);
    relout_kernel<<<R2, 128>>>(rel_repr, w_rel, out);
}

// round 16
// speedup vs baseline: 1.0352x; 1.0266x over previous
#include <cuda_runtime.h>
#include <cuda_bf16.h>
#include <math.h>
#include <stdint.h>

// Problem constants
#define NV 50000
#define NE 640000
#define NHALF 320000
#define TILE_E 64
#define HALF_TILES (NHALF/TILE_E)   // 5000
#define GRID_HALF 148
#define R2 474
#define FIN 128
#define FOUT 128
#define CSTR 132                    // node-kernel padded fp32 stride

// edge-kernel smem layout (bytes); bf16 row stride 272B (17x16B -> LDSM conflict-free)
#define QSTRB 272
#define SM_QHI   0
#define SM_QLO   34816              // 128*272
#define SM_AHI   69632
#define SM_ALO   87040              // + 64*272
#define SM_SCALE 104448             // 256 floats
#define SM_DST   105472             // 64 ints
#define EDGE_SMEM 105728

// ---------------- scratch ----------------------------------------------------
__device__ float g_hacc[(size_t)NV * FOUT];
__device__ float g_h2[(size_t)NV * FOUT];
__device__ __align__(16) float g_Qin[FIN * FOUT];
__device__ __align__(16) float g_Qout[FIN * FOUT];
__device__ __align__(16) float g_w1a[FIN * 4];
__device__ __align__(16) float g_w2a[FIN * 4];
__device__ __align__(16) float g_ndot[(size_t)NV * 4];   // x_v . w2a[:,k]
__device__ float g_sum[FOUT];
__device__ float g_sumsq[FOUT];

// ---------------- helpers -----------------------------------------------------
__device__ __forceinline__ uint32_t smem_u32(const void* p) {
    uint32_t a;
    asm("{ .reg .u64 t; cvta.to.shared.u64 t, %1; cvt.u32.u64 %0, t; }" : "=r"(a) : "l"(p));
    return a;
}
__device__ __forceinline__ void ldsm_x4(uint32_t& r0, uint32_t& r1, uint32_t& r2,
                                        uint32_t& r3, uint32_t addr) {
    asm volatile("ldmatrix.sync.aligned.m8n8.x4.shared.b16 {%0,%1,%2,%3}, [%4];"
                 : "=r"(r0), "=r"(r1), "=r"(r2), "=r"(r3) : "r"(addr));
}
__device__ __forceinline__ void mma_bf16(float* c, const uint32_t* a,
                                         uint32_t b0, uint32_t b1) {
    asm volatile(
        "mma.sync.aligned.m16n8k16.row.col.f32.bf16.bf16.f32 "
        "{%0,%1,%2,%3}, {%4,%5,%6,%7}, {%8,%9}, {%0,%1,%2,%3};"
        : "+f"(c[0]), "+f"(c[1]), "+f"(c[2]), "+f"(c[3])
        : "r"(a[0]), "r"(a[1]), "r"(a[2]), "r"(a[3]), "r"(b0), "r"(b1));
}

// ---------------- kernel 0: zero scratch -------------------------------------
__global__ void zero_kernel() {
    int idx = blockIdx.x * blockDim.x + threadIdx.x;
    const int n4 = NV * FOUT / 4;
    float4 z = make_float4(0.f, 0.f, 0.f, 0.f);
    for (int i = idx; i < n4; i += gridDim.x * blockDim.x)
        ((float4*)g_hacc)[i] = z;
    if (idx < FOUT) { g_sum[idx] = 0.f; g_sumsq[idx] = 0.f; }
}

// ---------------- kernel 1a: fold attention weights --------------------------
__global__ void wfold_kernel(const float* __restrict__ node_w,
                             const float* __restrict__ node_rel_w,
                             const float* __restrict__ att_w) {
    int i = threadIdx.x;
    if (i >= 128) return;
#pragma unroll
    for (int k = 0; k < 4; k++) {
        float s1 = 0.f, s2 = 0.f;
#pragma unroll
        for (int d = 0; d < 32; d++) {
            s1 = fmaf(node_rel_w[k * 4096 + i * 32 + d], att_w[d], s1);
            s2 = fmaf(node_w[k * 4096 + i * 32 + d], att_w[32 + d], s2);
        }
        g_w1a[i * 4 + k] = s1;
        g_w2a[i * 4 + k] = s2;
    }
}

// ---------------- kernel 1b: fold projection weights -------------------------
__global__ void qfold_kernel(const float* __restrict__ node_rel_w,
                             const float* __restrict__ in_w,
                             const float* __restrict__ out_w) {
    __shared__ float nrw_s[128];
    int i = blockIdx.x;
    int tid = threadIdx.x;
    {
        int k = tid >> 5, d = tid & 31;
        nrw_s[tid] = node_rel_w[k * 4096 + i * 32 + d];
    }
    __syncthreads();
    int k = tid >> 5, o = tid & 31;
    float qi = 0.f, qo = 0.f;
#pragma unroll
    for (int d = 0; d < 32; d++) {
        float w = nrw_s[k * 32 + d];
        qi = fmaf(w, in_w[k * 1024 + d * 32 + o], qi);
        qo = fmaf(w, out_w[k * 1024 + d * 32 + o], qo);
    }
    g_Qin[i * 128 + tid] = qi;
    g_Qout[i * 128 + tid] = qo;
}

// ---------------- kernel 1c: per-node dst attention term (4 nodes/warp) ------
__global__ void ndot_kernel(const float* __restrict__ node_repr) {
    int gwarp = (blockIdx.x * blockDim.x + threadIdx.x) >> 5;
    int lane = threadIdx.x & 31;
    int sub = lane >> 3;
    int l8 = lane & 7;
    int node = gwarp * 4 + sub;
    if (node >= NV) return;
    const float4* xr = (const float4*)(node_repr + (size_t)node * 128);
    const float4* w2 = (const float4*)g_w2a;
    float s0 = 0.f, s1 = 0.f, s2 = 0.f, s3 = 0.f;
#pragma unroll
    for (int j = 0; j < 4; j++) {
        float4 x = xr[l8 + 8 * j];
        const float4* wrow = w2 + (l8 + 8 * j) * 4;
        float4 wv;
        wv = wrow[0]; s0 = fmaf(x.x, wv.x, s0); s1 = fmaf(x.x, wv.y, s1); s2 = fmaf(x.x, wv.z, s2); s3 = fmaf(x.x, wv.w, s3);
        wv = wrow[1]; s0 = fmaf(x.y, wv.x, s0); s1 = fmaf(x.y, wv.y, s1); s2 = fmaf(x.y, wv.z, s2); s3 = fmaf(x.y, wv.w, s3);
        wv = wrow[2]; s0 = fmaf(x.z, wv.x, s0); s1 = fmaf(x.z, wv.y, s1); s2 = fmaf(x.z, wv.z, s2); s3 = fmaf(x.z, wv.w, s3);
        wv = wrow[3]; s0 = fmaf(x.w, wv.x, s0); s1 = fmaf(x.w, wv.y, s1); s2 = fmaf(x.w, wv.z, s2); s3 = fmaf(x.w, wv.w, s3);
    }
#pragma unroll
    for (int off = 1; off < 8; off <<= 1) {
        s0 += __shfl_xor_sync(0xFFFFFFFFu, s0, off);
        s1 += __shfl_xor_sync(0xFFFFFFFFu, s1, off);
        s2 += __shfl_xor_sync(0xFFFFFFFFu, s2, off);
        s3 += __shfl_xor_sync(0xFFFFFFFFu, s3, off);
    }
    if (l8 == 0)
        ((float4*)g_ndot)[node] = make_float4(s0, s1, s2, s3);
}

// ---------------- kernel 2: edge kernel (rb=2 x cb=4 warp tiling) ------------
// Warp tile = 32 edges x 32 cols; B frags hoisted per k-step and reused across
// both m16 fragments -> LDSM bytes per tile 320KB -> 256KB. Gather/logits/
// scatter structure identical to the round-13/15 champion.
__global__ void __launch_bounds__(256, 2) edge_kernel(
    const float* __restrict__ node_repr, const float* __restrict__ rel_repr,
    const int* __restrict__ src, const int* __restrict__ dst,
    const int* __restrict__ etype, const float* __restrict__ nrm) {
    extern __shared__ __align__(16) char smem[];
    uint32_t sb = smem_u32(smem);
    float* s_scale = (float*)(smem + SM_SCALE);
    int*   s_dst   = (int*)(smem + SM_DST);

    int tid = threadIdx.x;
    int wid = tid >> 5;
    int lane = tid & 31;
    int cta = blockIdx.x;
    int halfsel = (cta >= GRID_HALF) ? 1 : 0;
    int tile0 = cta - halfsel * GRID_HALF;
    const float* Q = halfsel ? g_Qout : g_Qin;

    // ---- stage Q as bf16 hi/lo, [n_phys][k], with intra-16-block column perm ----
    for (int idx = tid; idx < 16384; idx += 256) {
        int n = idx >> 7, k = idx & 127;
        int o = n & 15;
        int real = (n & ~15) | (((o & 6) << 1) | ((o & 8) >> 2) | (o & 1));
        float v = Q[k * 128 + real];
        __nv_bfloat16 hi = __float2bfloat16(v);
        __nv_bfloat16 lo = __float2bfloat16(v - __bfloat162float(hi));
        *(__nv_bfloat16*)(smem + SM_QHI + n * QSTRB + k * 2) = hi;
        *(__nv_bfloat16*)(smem + SM_QLO + n * QSTRB + k * 2) = lo;
    }

    // gather mapping: 4 threads per edge, interleaved 4-float slices
    int e    = tid >> 2;
    int l4   = tid & 3;

    // warp tiling: 2 row-bands (32 edges) x 4 col-bands (32 cols)
    int rb = wid & 1, cb = wid >> 1;
    int eb = rb * 32;
    int nb0 = cb * 32;     // whole warp tile inside k-factor cb

    // ldmatrix lane addressing
    int arin = lane & 7;
    uint32_t a_rowl = (uint32_t)(((lane >> 3) & 1) * 8 + arin);
    uint32_t a_coff = (uint32_t)((lane >> 4) * 16);
    uint32_t b_row  = (uint32_t)((lane >> 4) * 8 + arin);
    uint32_t b_coff = (uint32_t)(((lane >> 3) & 1) * 16);

    for (int t = tile0; t < HALF_TILES; t += GRID_HALF) {
        __syncthreads();   // prior tile fully consumed (GEMM + scatter done)
        int e0 = (t + halfsel * HALF_TILES) * TILE_E;

        // ---- gather + compose + logits; store comp bf16 hi/lo ----
        {
            int isrc = __ldg(src + e0 + e);
            int idst = __ldg(dst + e0 + e);
            int iet  = __ldg(etype + e0 + e);
            float nv = __ldg(nrm + e0 + e);
            if (l4 == 0) s_dst[e] = idst;

            const float4* xs = (const float4*)(node_repr + (size_t)isrc * 128) + l4;
            const float4* rr = (const float4*)(rel_repr  + (size_t)iet  * 128) + l4;
            const float4* w1 = ((const float4*)g_w1a) + l4 * 4;
            float lg0 = 0.f, lg1 = 0.f, lg2 = 0.f, lg3 = 0.f;
#pragma unroll 4
            for (int q = 0; q < 8; q++) {
                float4 a = xs[q * 4], r4 = rr[q * 4];
                float4 c;
                c.x = a.x * r4.x; c.y = a.y * r4.y; c.z = a.z * r4.z; c.w = a.w * r4.w;
                {
                    __nv_bfloat162 h01 = __floats2bfloat162_rn(c.x, c.y);
                    __nv_bfloat162 h23 = __floats2bfloat162_rn(c.z, c.w);
                    __nv_bfloat162 l01 = __floats2bfloat162_rn(
                        c.x - __bfloat162float(h01.x), c.y - __bfloat162float(h01.y));
                    __nv_bfloat162 l23 = __floats2bfloat162_rn(
                        c.z - __bfloat162float(h23.x), c.w - __bfloat162float(h23.y));
                    uint32_t coff = (uint32_t)(e * QSTRB + (l4 * 4 + q * 16) * 2);
                    uint2 hv, lv;
                    hv.x = *(uint32_t*)&h01; hv.y = *(uint32_t*)&h23;
                    lv.x = *(uint32_t*)&l01; lv.y = *(uint32_t*)&l23;
                    *(uint2*)(smem + SM_AHI + coff) = hv;
                    *(uint2*)(smem + SM_ALO + coff) = lv;
                }
                int ib = q * 16;
                float4 wv;
                wv = w1[ib + 0]; lg0 = fmaf(c.x, wv.x, lg0); lg1 = fmaf(c.x, wv.y, lg1); lg2 = fmaf(c.x, wv.z, lg2); lg3 = fmaf(c.x, wv.w, lg3);
                wv = w1[ib + 1]; lg0 = fmaf(c.y, wv.x, lg0); lg1 = fmaf(c.y, wv.y, lg1); lg2 = fmaf(c.y, wv.z, lg2); lg3 = fmaf(c.y, wv.w, lg3);
                wv = w1[ib + 2]; lg0 = fmaf(c.z, wv.x, lg0); lg1 = fmaf(c.z, wv.y, lg1); lg2 = fmaf(c.z, wv.z, lg2); lg3 = fmaf(c.z, wv.w, lg3);
                wv = w1[ib + 3]; lg0 = fmaf(c.w, wv.x, lg0); lg1 = fmaf(c.w, wv.y, lg1); lg2 = fmaf(c.w, wv.z, lg2); lg3 = fmaf(c.w, wv.w, lg3);
            }
            lg0 += __shfl_xor_sync(0xFFFFFFFFu, lg0, 1);
            lg1 += __shfl_xor_sync(0xFFFFFFFFu, lg1, 1);
            lg2 += __shfl_xor_sync(0xFFFFFFFFu, lg2, 1);
            lg3 += __shfl_xor_sync(0xFFFFFFFFu, lg3, 1);
            lg0 += __shfl_xor_sync(0xFFFFFFFFu, lg0, 2);
            lg1 += __shfl_xor_sync(0xFFFFFFFFu, lg1, 2);
            lg2 += __shfl_xor_sync(0xFFFFFFFFu, lg2, 2);
            lg3 += __shfl_xor_sync(0xFFFFFFFFu, lg3, 2);
            if (l4 == 0) {
                float4 nd = __ldg(((const float4*)g_ndot) + idst);
                float l0 = fmaxf(lg0 + nd.x, 0.f);
                float l1 = fmaxf(lg1 + nd.y, 0.f);
                float l2 = fmaxf(lg2 + nd.z, 0.f);
                float l3 = fmaxf(lg3 + nd.w, 0.f);
                float e0x = expf(l0), e1x = expf(l1), e2x = expf(l2), e3x = expf(l3);
                float inv = nv / (e0x + e1x + e2x + e3x);   // /3 applied in node kernel
                s_scale[e * 4 + 0] = e0x * inv;
                s_scale[e * 4 + 1] = e1x * inv;
                s_scale[e * 4 + 2] = e2x * inv;
                s_scale[e * 4 + 3] = e3x * inv;
            }
        }
        __syncthreads();

        // ---- GEMM: 32 edges x 32 cols per warp, K=128, 3 bf16-split passes ----
        // c[mf][nt]: mf = m16 fragment (0,1), nt = blk*2 + frag (4 per mf)
        float c[2][4][4];
#pragma unroll
        for (int mf = 0; mf < 2; mf++)
#pragma unroll
            for (int nt = 0; nt < 4; nt++)
#pragma unroll
                for (int j = 0; j < 4; j++) c[mf][nt][j] = 0.f;

#pragma unroll 1
        for (int k = 0; k < 8; k++) {
            // hoist B for both n16 blocks (hi + lo), reused across both mf
            uint32_t bh0[4], bl0[4], bh1[4], bl1[4];
            {
                uint32_t boff0 = (uint32_t)(nb0 + b_row) * QSTRB + b_coff + k * 32;
                uint32_t boff1 = (uint32_t)(nb0 + 16 + b_row) * QSTRB + b_coff + k * 32;
                ldsm_x4(bh0[0], bh0[1], bh0[2], bh0[3], sb + SM_QHI + boff0);
                ldsm_x4(bl0[0], bl0[1], bl0[2], bl0[3], sb + SM_QLO + boff0);
                ldsm_x4(bh1[0], bh1[1], bh1[2], bh1[3], sb + SM_QHI + boff1);
                ldsm_x4(bl1[0], bl1[1], bl1[2], bl1[3], sb + SM_QLO + boff1);
            }
#pragma unroll
            for (int mf = 0; mf < 2; mf++) {
                uint32_t aoff = (uint32_t)(eb + mf * 16 + a_rowl) * QSTRB + a_coff + k * 32;
                uint32_t ahi[4], alo[4];
                ldsm_x4(ahi[0], ahi[1], ahi[2], ahi[3], sb + SM_AHI + aoff);
                ldsm_x4(alo[0], alo[1], alo[2], alo[3], sb + SM_ALO + aoff);
                // round-13 proven chain order per fragment
                mma_bf16(c[mf][0], ahi, bh0[0], bh0[1]);
                mma_bf16(c[mf][0], ahi, bl0[0], bl0[1]);
                mma_bf16(c[mf][0], alo, bh0[0], bh0[1]);
                mma_bf16(c[mf][1], ahi, bh0[2], bh0[3]);
                mma_bf16(c[mf][1], ahi, bl0[2], bl0[3]);
                mma_bf16(c[mf][1], alo, bh0[2], bh0[3]);
                mma_bf16(c[mf][2], ahi, bh1[0], bh1[1]);
                mma_bf16(c[mf][2], ahi, bl1[0], bl1[1]);
                mma_bf16(c[mf][2], alo, bh1[0], bh1[1]);
                mma_bf16(c[mf][3], ahi, bh1[2], bh1[3]);
                mma_bf16(c[mf][3], ahi, bl1[2], bl1[3]);
                mma_bf16(c[mf][3], alo, bh1[2], bh1[3]);
            }
        }

        // ---- scale + scatter: red.v4; whole warp tile in k-factor cb ----
        {
            int q4 = (lane & 3) * 4;
#pragma unroll
            for (int mf = 0; mf < 2; mf++) {
                int er0 = eb + mf * 16 + (lane >> 2);
                int er1 = er0 + 8;
                float s0 = s_scale[er0 * 4 + cb];
                float s1 = s_scale[er1 * 4 + cb];
                float* hp0 = g_hacc + (size_t)s_dst[er0] * 128;
                float* hp1 = g_hacc + (size_t)s_dst[er1] * 128;
#pragma unroll
                for (int blk = 0; blk < 2; blk++) {
                    int nbase = nb0 + blk * 16 + q4;
                    asm volatile("red.global.add.v4.f32 [%0], {%1, %2, %3, %4};"
                        :: "l"(hp0 + nbase),
                           "f"(c[mf][2 * blk][0] * s0), "f"(c[mf][2 * blk][1] * s0),
                           "f"(c[mf][2 * blk + 1][0] * s0), "f"(c[mf][2 * blk + 1][1] * s0)
                        : "memory");
                    asm volatile("red.global.add.v4.f32 [%0], {%1, %2, %3, %4};"
                        :: "l"(hp1 + nbase),
                           "f"(c[mf][2 * blk][2] * s1), "f"(c[mf][2 * blk][3] * s1),
                           "f"(c[mf][2 * blk + 1][2] * s1), "f"(c[mf][2 * blk + 1][3] * s1)
                        : "memory");
                }
            }
        }
    }
}

// ---------------- kernel 3: node kernel (self-loop GEMM + fused BN stats) ---
__global__ void __launch_bounds__(128) node_kernel(
    const float* __restrict__ loop_rel, const float* __restrict__ loop_w,
    const float* __restrict__ bias) {
    extern __shared__ float sm[];
    float* t      = sm;                 // 64*CSTR
    float* sh     = t + 64 * CSTR;      // 64*CSTR
    float* colsum = sh + 64 * CSTR;     // 128
    float* colsq  = colsum + 128;       // 128

    int tid = threadIdx.x;
    int row0 = blockIdx.x * 64;

    if (tid < 128) { colsum[tid] = 0.f; colsq[tid] = 0.f; }

    {
        int e = tid >> 1;
        int ioff = (tid & 1) * 64;
        int row = row0 + e;
        float* tp = t + e * CSTR + ioff;
        float* hp = sh + e * CSTR + ioff;
        if (row < NV) {
            const float4* hv4 = (const float4*)(g_hacc + (size_t)row * 128 + ioff);
            const float4* lr4 = (const float4*)(loop_rel + ioff);
#pragma unroll
            for (int q = 0; q < 16; q++) {
                float4 hh = hv4[q];
                hh.x *= (1.f / 3.f); hh.y *= (1.f / 3.f); hh.z *= (1.f / 3.f); hh.w *= (1.f / 3.f);
                *(float4*)(hp + q * 4) = hh;
                float4 lr = lr4[q];
                float4 tv;
                tv.x = hh.x * lr.x; tv.y = hh.y * lr.y; tv.z = hh.z * lr.z; tv.w = hh.w * lr.w;
                *(float4*)(tp + q * 4) = tv;
            }
        } else {
            float4 z = make_float4(0.f, 0.f, 0.f, 0.f);
#pragma unroll
            for (int q = 0; q < 16; q++) {
                *(float4*)(hp + q * 4) = z;
                *(float4*)(tp + q * 4) = z;
            }
        }
    }
    __syncthreads();

    int c4 = tid & 15, r = tid >> 4;
    float acc[8][8];
#pragma unroll
    for (int u = 0; u < 8; u++)
#pragma unroll
        for (int m = 0; m < 8; m++) acc[u][m] = 0.f;

    const float* ap = t + (r * 8) * CSTR;
    const float* bp = loop_w + c4 * 4;
#pragma unroll 1
    for (int k = 0; k < 128; k += 4) {
#pragma unroll
        for (int kk = 0; kk < 4; kk++) {
            const float* brow = bp + (k + kk) * 128;
            float4 b0 = __ldg((const float4*)brow);
            float4 b1 = __ldg((const float4*)(brow + 64));
            float bv[8];
            bv[0] = b0.x; bv[1] = b0.y; bv[2] = b0.z; bv[3] = b0.w;
            bv[4] = b1.x; bv[5] = b1.y; bv[6] = b1.z; bv[7] = b1.w;
#pragma unroll
            for (int u = 0; u < 8; u++) {
                float av = ap[u * CSTR + k + kk];
#pragma unroll
                for (int m = 0; m < 8; m++) acc[u][m] = fmaf(av, bv[m], acc[u][m]);
            }
        }
    }

    float psum[8], psq[8];
#pragma unroll
    for (int m = 0; m < 8; m++) { psum[m] = 0.f; psq[m] = 0.f; }
#pragma unroll
    for (int u = 0; u < 8; u++) {
        int e = r * 8 + u;
        int row = row0 + e;
        if (row < NV) {
#pragma unroll
            for (int m = 0; m < 8; m++) {
                int col = (m < 4) ? (c4 * 4 + m) : (64 + c4 * 4 + m - 4);
                float v = sh[e * CSTR + col] + acc[u][m] * (1.f / 3.f) + bias[col];
                g_h2[(size_t)row * 128 + col] = v;
                psum[m] += v;
                psq[m] = fmaf(v, v, psq[m]);
            }
        }
    }
#pragma unroll
    for (int m = 0; m < 8; m++) {
        int col = (m < 4) ? (c4 * 4 + m) : (64 + c4 * 4 + m - 4);
        atomicAdd(&colsum[col], psum[m]);
        atomicAdd(&colsq[col], psq[m]);
    }
    __syncthreads();
    if (tid < 128) {
        atomicAdd(&g_sum[tid], colsum[tid]);
        atomicAdd(&g_sumsq[tid], colsq[tid]);
    }
}

// ---------------- kernel 4: batchnorm + tanh ---------------------------------
__global__ void finalize_kernel(const float* __restrict__ gamma,
                                const float* __restrict__ beta,
                                float* __restrict__ out) {
    __shared__ float sa[128], sb_[128];
    int tid = threadIdx.x;
    if (tid < 128) {
        float mean = g_sum[tid] * (1.f / NV);
        float var = g_sumsq[tid] * (1.f / NV) - mean * mean;
        float a = gamma[tid] * rsqrtf(var + 1e-5f);
        sa[tid] = a;
        sb_[tid] = beta[tid] - mean * a;
    }
    __syncthreads();
    const int n4 = NV * FOUT / 4;
    for (int i = blockIdx.x * blockDim.x + tid; i < n4; i += gridDim.x * blockDim.x) {
        float4 v = ((const float4*)g_h2)[i];
        int c0 = (i * 4) & 127;
        float4 y;
        y.x = tanhf(fmaf(v.x, sa[c0 + 0], sb_[c0 + 0]));
        y.y = tanhf(fmaf(v.y, sa[c0 + 1], sb_[c0 + 1]));
        y.z = tanhf(fmaf(v.z, sa[c0 + 2], sb_[c0 + 2]));
        y.w = tanhf(fmaf(v.w, sa[c0 + 3], sb_[c0 + 3]));
        ((float4*)out)[i] = y;
    }
}

// ---------------- kernel 5: rel_out = rel_repr @ w_rel -----------------------
__global__ void relout_kernel(const float* __restrict__ rel_repr,
                              const float* __restrict__ w_rel,
                              float* __restrict__ out) {
    __shared__ float rrow[128];
    int b = blockIdx.x, tid = threadIdx.x;
    rrow[tid] = rel_repr[b * 128 + tid];
    __syncthreads();
    float s = 0.f;
#pragma unroll 4
    for (int i = 0; i < 128; i++) s = fmaf(rrow[i], w_rel[i * 128 + tid], s);
    out[(size_t)NV * FOUT + b * 128 + tid] = s;
}

// ---------------- host launcher ----------------------------------------------
extern "C" void kernel_launch(void* const* d_in, const int* in_sizes, int n_in,
                              void* d_out, int out_size) {
    const float* node_repr  = (const float*)d_in[0];
    const float* rel_repr   = (const float*)d_in[1];
    const int*   src        = (const int*)d_in[2];
    const int*   dst        = (const int*)d_in[3];
    const int*   etype      = (const int*)d_in[4];
    const float* nrm        = (const float*)d_in[5];
    const float* node_w     = (const float*)d_in[6];
    const float* node_rel_w = (const float*)d_in[7];
    const float* in_w       = (const float*)d_in[8];
    const float* out_w      = (const float*)d_in[9];
    const float* att_w      = (const float*)d_in[10];
    const float* loop_rel   = (const float*)d_in[11];
    const float* loop_w     = (const float*)d_in[12];
    const float* w_rel      = (const float*)d_in[13];
    const float* bias       = (const float*)d_in[14];
    const float* bn_gamma   = (const float*)d_in[15];
    const float* bn_beta    = (const float*)d_in[16];
    float* out = (float*)d_out;

    static const int NODE_SMEM = (2 * 64 * CSTR + 256) * 4;   // ~68.6 KB -> 3 CTAs/SM
    cudaFuncSetAttribute(edge_kernel, cudaFuncAttributeMaxDynamicSharedMemorySize, EDGE_SMEM);
    cudaFuncSetAttribute(node_kernel, cudaFuncAttributeMaxDynamicSharedMemorySize, NODE_SMEM);

    zero_kernel<<<512, 256>>>();
    wfold_kernel<<<1, 128>>>(node_w, node_rel_w, att_w);
    qfold_kernel<<<128, 128>>>(node_rel_w, in_w, out_w);
    ndot_kernel<<<(NV / 4 + 7) / 8 + 1, 256>>>(node_repr);
    edge_kernel<<<2 * GRID_HALF, 256, EDGE_SMEM>>>(node_repr, rel_repr, src, dst, etype, nrm);
    node_kernel<<<(NV + 63) / 64, 128, NODE_SMEM>>>(loop_rel, loop_w, bias);
    finalize_kernel<<<1024, 256>>>(bn_gamma, bn_beta, out);
    relout_kernel<<<R2, 128>>>(rel_repr, w_rel, out);
}